// round 1
// baseline (speedup 1.0000x reference)
#include <cuda_runtime.h>
#include <cuda_bf16.h>
#include <cstdint>

// Problem constants
#define BB 4
#define TT 1024
#define CC 512
#define HH 8
#define DD 64
#define NROWS (BB*TT)          // 4096
#define C3 (3*CC)              // 1536
#define NEGF (-3.402823466e38f)

// -------- scratch (static device globals; allocation-free) --------
__device__ float g_xn[(size_t)NROWS*CC];          // 8 MB
__device__ float g_qkv[(size_t)NROWS*C3];         // 24 MB
__device__ float g_biasT[(size_t)BB*HH*TT*TT];    // 128 MB
__device__ float g_attn[(size_t)NROWS*CC];        // 8 MB
__device__ int   g_mask_kind;                     // 0=int32, 1=float32, 2=uint8

// ---------------- LayerNorm over 512 (one block per row) ----------------
__device__ __forceinline__ float warp_sum(float v) {
    #pragma unroll
    for (int o = 16; o; o >>= 1) v += __shfl_xor_sync(0xffffffffu, v, o);
    return v;
}

__global__ void ln_kernel(const float* src, const float* __restrict__ w,
                          const float* __restrict__ b, float* dst,
                          int sstride, int soff, int dstride, int doff)
{
    int row = blockIdx.x;
    const float* xr = src + (size_t)row * sstride + soff;
    float* yr = dst + (size_t)row * dstride + doff;
    int t = threadIdx.x;  // 128 threads, 4 floats each
    float4 v = *(const float4*)(xr + t * 4);
    float s  = v.x + v.y + v.z + v.w;
    float sq = v.x*v.x + v.y*v.y + v.z*v.z + v.w*v.w;
    s = warp_sum(s); sq = warp_sum(sq);
    __shared__ float sh[8];
    int wid = t >> 5, lid = t & 31;
    if (lid == 0) { sh[wid] = s; sh[4 + wid] = sq; }
    __syncthreads();
    float ts = sh[0] + sh[1] + sh[2] + sh[3];
    float tq = sh[4] + sh[5] + sh[6] + sh[7];
    float mean = ts * (1.f / CC);
    float var  = tq * (1.f / CC) - mean * mean;
    float rstd = rsqrtf(var + 1e-5f);
    float4 wv = *(const float4*)(w + t * 4);
    float4 bv = *(const float4*)(b + t * 4);
    float4 o;
    o.x = (v.x - mean) * rstd * wv.x + bv.x;
    o.y = (v.y - mean) * rstd * wv.y + bv.y;
    o.z = (v.z - mean) * rstd * wv.z + bv.z;
    o.w = (v.w - mean) * rstd * wv.w + bv.w;
    *(float4*)(yr + t * 4) = o;
}

// ---------------- SGEMM NT: C[m,n] = sum_k A[m,k]*B[n,k] + bias[n] ----------------
// BM=BN=128, BK=8, 256 threads, 8x8 per thread.
__global__ __launch_bounds__(256, 2)
void sgemm_nt(const float* __restrict__ A, const float* __restrict__ Bm,
              const float* __restrict__ bias, float* __restrict__ C,
              int M, int N, int K)
{
    __shared__ float As[8][128];
    __shared__ float Bs[8][128];
    int tid = threadIdx.x;
    int tx = tid & 15;        // n direction (16)
    int ty = tid >> 4;        // m direction (16)
    int m0 = blockIdx.y * 128;
    int n0 = blockIdx.x * 128;
    int arow = tid >> 1;      // 0..127
    int akq  = tid & 1;       // 0..1 (which float4 along K)

    float acc[8][8];
    #pragma unroll
    for (int i = 0; i < 8; i++)
        #pragma unroll
        for (int j = 0; j < 8; j++) acc[i][j] = 0.f;

    const float* Aptr = A + (size_t)(m0 + arow) * K + akq * 4;
    const float* Bptr = Bm + (size_t)(n0 + arow) * K + akq * 4;

    for (int k0 = 0; k0 < K; k0 += 8) {
        float4 av = *(const float4*)(Aptr + k0);
        float4 bv = *(const float4*)(Bptr + k0);
        __syncthreads();
        As[akq*4+0][arow] = av.x; As[akq*4+1][arow] = av.y;
        As[akq*4+2][arow] = av.z; As[akq*4+3][arow] = av.w;
        Bs[akq*4+0][arow] = bv.x; Bs[akq*4+1][arow] = bv.y;
        Bs[akq*4+2][arow] = bv.z; Bs[akq*4+3][arow] = bv.w;
        __syncthreads();
        #pragma unroll
        for (int kk = 0; kk < 8; kk++) {
            float af[8], bf[8];
            #pragma unroll
            for (int u = 0; u < 4; u++) {
                af[u]     = As[kk][ty*8 + u];
                af[u+4]   = As[kk][ty*8 + 4 + u];
                bf[u]     = Bs[kk][tx*8 + u];
                bf[u+4]   = Bs[kk][tx*8 + 4 + u];
            }
            #pragma unroll
            for (int i = 0; i < 8; i++)
                #pragma unroll
                for (int j = 0; j < 8; j++)
                    acc[i][j] += af[i] * bf[j];
        }
    }

    // epilogue with bias
    float4 bsv0 = *(const float4*)(bias + n0 + tx*8);
    float4 bsv1 = *(const float4*)(bias + n0 + tx*8 + 4);
    #pragma unroll
    for (int i = 0; i < 8; i++) {
        int row = m0 + ty*8 + i;
        float4 o0, o1;
        o0.x = acc[i][0] + bsv0.x; o0.y = acc[i][1] + bsv0.y;
        o0.z = acc[i][2] + bsv0.z; o0.w = acc[i][3] + bsv0.w;
        o1.x = acc[i][4] + bsv1.x; o1.y = acc[i][5] + bsv1.y;
        o1.z = acc[i][6] + bsv1.z; o1.w = acc[i][7] + bsv1.w;
        *(float4*)(C + (size_t)row * N + n0 + tx*8)     = o0;
        *(float4*)(C + (size_t)row * N + n0 + tx*8 + 4) = o1;
    }
}

// ---------------- mask dtype detection ----------------
__global__ void detect_mask_kind(const void* mask)
{
    __shared__ int s_int, s_float;
    if (threadIdx.x == 0) { s_int = 1; s_float = 1; }
    __syncthreads();
    const unsigned int* w = (const unsigned int*)mask;
    int ok_i = 1, ok_f = 1;
    for (int i = threadIdx.x; i < 1024; i += blockDim.x) {
        unsigned int v = w[i];
        if (v > 1u) ok_i = 0;
        if (v != 0u && v != 0x3F800000u) ok_f = 0;
    }
    atomicAnd(&s_int, ok_i);
    atomicAnd(&s_float, ok_f);
    __syncthreads();
    if (threadIdx.x == 0) g_mask_kind = s_int ? 0 : (s_float ? 1 : 2);
}

// ---------------- pair [B,T,T,H] -> biasT [B,H,T,T], folding mask ----------------
// grid (T/128, T, B), 256 threads
__global__ void bias_transpose_kernel(const float* __restrict__ pair,
                                      const void* __restrict__ mask)
{
    __shared__ float sp[128][9];   // pad 9 -> conflict-free transposed reads
    __shared__ float addm[128];
    int b = blockIdx.z, i = blockIdx.y, j0 = blockIdx.x * 128;
    int t = threadIdx.x;

    const float* src = pair + (((size_t)(b * TT + i) * TT) + j0) * HH;
    {
        int f = t * 4;              // 0..1023
        int tj = f >> 3;
        int h0 = f & 7;             // 0 or 4
        float4 v = *(const float4*)(src + f);
        sp[tj][h0]   = v.x; sp[tj][h0+1] = v.y;
        sp[tj][h0+2] = v.z; sp[tj][h0+3] = v.w;
    }
    if (t < 128) {
        size_t mi = ((size_t)(b * TT + i)) * TT + j0 + t;
        int kind = g_mask_kind;
        bool mv;
        if (kind == 0)      mv = ((const int*)mask)[mi] != 0;
        else if (kind == 1) mv = ((const float*)mask)[mi] != 0.f;
        else                mv = ((const unsigned char*)mask)[mi] != 0;
        addm[t] = mv ? 0.f : NEGF;
    }
    __syncthreads();
    #pragma unroll
    for (int u = 0; u < 4; u++) {
        int f = t + 256 * u;        // 0..1023
        int h = f >> 7;
        int tj = f & 127;
        g_biasT[(((size_t)(b * HH + h) * TT + i) * TT) + j0 + tj] = sp[tj][h] + addm[tj];
    }
}

// ---------------- flash attention: one thread per Q row ----------------
// grid (T/128, B*H), 128 threads
__global__ __launch_bounds__(128, 2)
void flash_kernel(const float* __restrict__ qkv, float* __restrict__ out)
{
    __shared__ float Ks[32][64];
    __shared__ float Vs[32][64];
    __shared__ float Bsm[128][33];  // pad 33 -> conflict-free per-row reads

    int tidx = threadIdx.x;
    int bh = blockIdx.y;
    int b = bh >> 3, h = bh & 7;
    int i0 = blockIdx.x * 128;
    int i = i0 + tidx;
    const float scale = 0.125f;     // D^-0.5 / TEMP

    float qv[64];
    const float* qrow = qkv + (size_t)(b * TT + i) * C3 + h * DD;
    #pragma unroll
    for (int d = 0; d < 64; d += 4) {
        float4 t = *(const float4*)(qrow + d);
        qv[d] = t.x * scale; qv[d+1] = t.y * scale;
        qv[d+2] = t.z * scale; qv[d+3] = t.w * scale;
    }

    float m = -3.0e38f, l = 0.f;
    float acc[64];
    #pragma unroll
    for (int d = 0; d < 64; d++) acc[d] = 0.f;

    const float* kbase = qkv + (size_t)b * TT * C3 + CC + h * DD;
    const float* vbase = kbase + CC;
    const float* bbase = g_biasT + ((size_t)bh * TT + i0) * TT;

    for (int jt = 0; jt < 32; jt++) {
        int j0 = jt * 32;
        __syncthreads();
        // K/V tiles: 512 float4 each, 4 per thread
        #pragma unroll
        for (int u = 0; u < 4; u++) {
            int f = tidx * 4 + u;        // 0..511
            int jj = f >> 4;
            int dd = (f & 15) << 2;
            *(float4*)&Ks[jj][dd] = *(const float4*)(kbase + (size_t)(j0 + jj) * C3 + dd);
            *(float4*)&Vs[jj][dd] = *(const float4*)(vbase + (size_t)(j0 + jj) * C3 + dd);
        }
        // bias tile 128x32: 1024 float4, 8 per thread
        #pragma unroll
        for (int u = 0; u < 8; u++) {
            int f = tidx * 8 + u;        // 0..1023
            int r = f >> 3;
            int c = (f & 7) << 2;
            float4 bv = *(const float4*)(bbase + (size_t)r * TT + j0 + c);
            Bsm[r][c] = bv.x; Bsm[r][c+1] = bv.y;
            Bsm[r][c+2] = bv.z; Bsm[r][c+3] = bv.w;
        }
        __syncthreads();

        float s[32];
        #pragma unroll
        for (int jj = 0; jj < 32; jj++) {
            float dot = 0.f;
            #pragma unroll
            for (int dd = 0; dd < 64; dd += 4) {
                float4 kv = *(const float4*)&Ks[jj][dd];
                dot += qv[dd] * kv.x + qv[dd+1] * kv.y
                     + qv[dd+2] * kv.z + qv[dd+3] * kv.w;
            }
            s[jj] = dot + Bsm[tidx][jj];
        }
        float tmax = s[0];
        #pragma unroll
        for (int jj = 1; jj < 32; jj++) tmax = fmaxf(tmax, s[jj]);
        float mnew = fmaxf(m, tmax);
        float corr = __expf(m - mnew);
        l *= corr;
        #pragma unroll
        for (int d = 0; d < 64; d++) acc[d] *= corr;
        #pragma unroll
        for (int jj = 0; jj < 32; jj++) {
            float p = __expf(s[jj] - mnew);
            l += p;
            #pragma unroll
            for (int dd = 0; dd < 64; dd += 4) {
                float4 vv = *(const float4*)&Vs[jj][dd];
                acc[dd]   += p * vv.x; acc[dd+1] += p * vv.y;
                acc[dd+2] += p * vv.z; acc[dd+3] += p * vv.w;
            }
        }
        m = mnew;
    }

    float inv = 1.f / l;
    float* orow = out + (size_t)(b * TT + i) * CC + h * DD;
    #pragma unroll
    for (int d = 0; d < 64; d += 4) {
        float4 o;
        o.x = acc[d] * inv;   o.y = acc[d+1] * inv;
        o.z = acc[d+2] * inv; o.w = acc[d+3] * inv;
        *(float4*)(orow + d) = o;
    }
}

// ---------------- launch ----------------
extern "C" void kernel_launch(void* const* d_in, const int* in_sizes, int n_in,
                              void* d_out, int out_size)
{
    const float* x      = (const float*)d_in[0];
    const float* pair   = (const float*)d_in[1];
    const void*  mask   = d_in[2];
    const float* norm_w = (const float*)d_in[3];
    const float* norm_b = (const float*)d_in[4];
    const float* qkv_w  = (const float*)d_in[5];
    const float* qkv_b  = (const float*)d_in[6];
    const float* qln_w  = (const float*)d_in[7];
    const float* qln_b  = (const float*)d_in[8];
    const float* kln_w  = (const float*)d_in[9];
    const float* kln_b  = (const float*)d_in[10];
    const float* proj_w = (const float*)d_in[11];
    const float* proj_b = (const float*)d_in[12];
    float* out = (float*)d_out;

    float *xn, *qkvp, *attn;
    cudaGetSymbolAddress((void**)&xn,   g_xn);
    cudaGetSymbolAddress((void**)&qkvp, g_qkv);
    cudaGetSymbolAddress((void**)&attn, g_attn);

    // 1. pre-norm
    ln_kernel<<<NROWS, 128>>>(x, norm_w, norm_b, xn, CC, 0, CC, 0);
    // 2. QKV GEMM [4096,1536]
    sgemm_nt<<<dim3(C3/128, NROWS/128), 256>>>(xn, qkv_w, qkv_b, qkvp, NROWS, C3, CC);
    // 3. q / k LayerNorm in place
    ln_kernel<<<NROWS, 128>>>(qkvp, qln_w, qln_b, qkvp, C3, 0,  C3, 0);
    ln_kernel<<<NROWS, 128>>>(qkvp, kln_w, kln_b, qkvp, C3, CC, C3, CC);
    // 4. mask dtype detection + pair transpose with mask fold
    detect_mask_kind<<<1, 256>>>(mask);
    bias_transpose_kernel<<<dim3(TT/128, TT, BB), 256>>>(pair, mask);
    // 5. flash attention -> [B,T,C]
    flash_kernel<<<dim3(TT/128, BB*HH), 128>>>(qkvp, attn);
    // 6. output projection
    sgemm_nt<<<dim3(CC/128, NROWS/128), 256>>>(attn, proj_w, proj_b, out, NROWS, CC, CC);
}

// round 3
// speedup vs baseline: 1.3549x; 1.3549x over previous
#include <cuda_runtime.h>
#include <cuda_bf16.h>
#include <cstdint>

// Problem constants
#define BB 4
#define TT 1024
#define CC 512
#define HH 8
#define DD 64
#define NROWS (BB*TT)          // 4096
#define C3 (3*CC)              // 1536
#define NEGF (-3.402823466e38f)

// -------- scratch (static device globals; allocation-free) --------
__device__ float g_qkv[(size_t)NROWS*C3];         // 24 MB
__device__ float g_biasT[(size_t)BB*HH*TT*TT];    // 128 MB
__device__ float g_attn[(size_t)NROWS*CC];        // 8 MB
__device__ int   g_mask_kind;                     // 0=int32, 1=float32, 2=uint8
// bf16 hi/lo split buffers
__device__ __nv_bfloat16 g_ah[(size_t)NROWS*CC];  // 4 MB
__device__ __nv_bfloat16 g_al[(size_t)NROWS*CC];  // 4 MB
__device__ __nv_bfloat16 g_wh[(size_t)C3*CC];     // 1.5 MB
__device__ __nv_bfloat16 g_wl[(size_t)C3*CC];     // 1.5 MB

// ================ generic-PTX tensor-core helpers ================
__device__ __forceinline__ uint32_t smem_u32(const void* p) {
    uint32_t a;
    asm("{ .reg .u64 t; cvta.to.shared.u64 t, %1; cvt.u32.u64 %0, t; }"
        : "=r"(a) : "l"(p));
    return a;
}
#define LDSM_X4(r0, r1, r2, r3, addr) \
    asm volatile("ldmatrix.sync.aligned.m8n8.x4.shared.b16 {%0,%1,%2,%3}, [%4];" \
        : "=r"(r0), "=r"(r1), "=r"(r2), "=r"(r3) : "r"(addr))
#define MMA_BF16(d, a, b) \
    asm volatile("mma.sync.aligned.m16n8k16.row.col.f32.bf16.bf16.f32 " \
        "{%0,%1,%2,%3}, {%4,%5,%6,%7}, {%8,%9}, {%0,%1,%2,%3};" \
        : "+f"((d)[0]), "+f"((d)[1]), "+f"((d)[2]), "+f"((d)[3]) \
        : "r"((a)[0]), "r"((a)[1]), "r"((a)[2]), "r"((a)[3]), \
          "r"((b)[0]), "r"((b)[1]))

// ================ LayerNorm over 512 (one block per row) ================
__device__ __forceinline__ float warp_sum(float v) {
    #pragma unroll
    for (int o = 16; o; o >>= 1) v += __shfl_xor_sync(0xffffffffu, v, o);
    return v;
}

__device__ __forceinline__ void ln_core(float4& v, const float* w, const float* b,
                                        int t, float4& o)
{
    float s  = v.x + v.y + v.z + v.w;
    float sq = v.x*v.x + v.y*v.y + v.z*v.z + v.w*v.w;
    s = warp_sum(s); sq = warp_sum(sq);
    __shared__ float sh[8];
    int wid = t >> 5, lid = t & 31;
    if (lid == 0) { sh[wid] = s; sh[4 + wid] = sq; }
    __syncthreads();
    float ts = sh[0] + sh[1] + sh[2] + sh[3];
    float tq = sh[4] + sh[5] + sh[6] + sh[7];
    float mean = ts * (1.f / CC);
    float var  = tq * (1.f / CC) - mean * mean;
    float rstd = rsqrtf(var + 1e-5f);
    float4 wv = *(const float4*)(w + t * 4);
    float4 bv = *(const float4*)(b + t * 4);
    o.x = (v.x - mean) * rstd * wv.x + bv.x;
    o.y = (v.y - mean) * rstd * wv.y + bv.y;
    o.z = (v.z - mean) * rstd * wv.z + bv.z;
    o.w = (v.w - mean) * rstd * wv.w + bv.w;
}

__global__ void ln_kernel(const float* src, const float* __restrict__ w,
                          const float* __restrict__ b, float* dst,
                          int sstride, int soff)
{
    int row = blockIdx.x;
    const float* xr = src + (size_t)row * sstride + soff;
    float* yr = dst + (size_t)row * sstride + soff;
    int t = threadIdx.x;
    float4 v = *(const float4*)(xr + t * 4);
    float4 o;
    ln_core(v, w, b, t, o);
    *(float4*)(yr + t * 4) = o;
}

// LN + bf16 hi/lo split (for pre-norm -> GEMM A operand)
__global__ void ln_split_kernel(const float* src, const float* __restrict__ w,
                                const float* __restrict__ b,
                                __nv_bfloat16* hi, __nv_bfloat16* lo)
{
    int row = blockIdx.x;
    const float* xr = src + (size_t)row * CC;
    int t = threadIdx.x;
    float4 v = *(const float4*)(xr + t * 4);
    float4 o;
    ln_core(v, w, b, t, o);
    size_t base = (size_t)row * CC + t * 4;
    float vv[4] = {o.x, o.y, o.z, o.w};
    #pragma unroll
    for (int u = 0; u < 4; u++) {
        __nv_bfloat16 h = __float2bfloat16(vv[u]);
        hi[base + u] = h;
        lo[base + u] = __float2bfloat16(vv[u] - __bfloat162float(h));
    }
}

// generic fp32 -> bf16 hi/lo split (vec4)
__global__ void split_kernel(const float* __restrict__ src,
                             __nv_bfloat16* hi, __nv_bfloat16* lo, int n4)
{
    int i = blockIdx.x * blockDim.x + threadIdx.x;
    if (i >= n4) return;
    float4 v = ((const float4*)src)[i];
    float vv[4] = {v.x, v.y, v.z, v.w};
    size_t base = (size_t)i * 4;
    #pragma unroll
    for (int u = 0; u < 4; u++) {
        __nv_bfloat16 h = __float2bfloat16(vv[u]);
        hi[base + u] = h;
        lo[base + u] = __float2bfloat16(vv[u] - __bfloat162float(h));
    }
}

// ================ HMMA bf16 split-GEMM ================
// C[m,n] = sum_k A[m,k]*B[n,k] + bias[n]; A/B as bf16 hi/lo pairs (K-major).
// CTA 128x128, 256 threads (8 warps 4x2), warp tile 32x64, BK=32.
// smem: 4 tiles [128 rows][32 bf16], row stride padded to 40 bf16 (80B) ->
// ldmatrix conflict-free (20*row+4*seg mod 32 spans all banks).
#define GT_STRIDE 80            // bytes per smem row
#define GT_TILE   (128*GT_STRIDE)   // 10240 B

__global__ __launch_bounds__(256, 1)
void gemm_tc16(const __nv_bfloat16* __restrict__ Ah, const __nv_bfloat16* __restrict__ Al,
               const __nv_bfloat16* __restrict__ Bh, const __nv_bfloat16* __restrict__ Bl,
               const float* __restrict__ bias, float* __restrict__ C,
               int N, int K)
{
    __shared__ __align__(16) char smem[4 * GT_TILE];  // 40 KB
    const int T_AH = 0, T_AL = GT_TILE, T_BH = 2*GT_TILE, T_BL = 3*GT_TILE;
    uint32_t sb = smem_u32(smem);

    int tid = threadIdx.x;
    int wid = tid >> 5, lane = tid & 31;
    int wm = wid >> 1, wn = wid & 1;        // 4 x 2 warp grid
    int gid = lane >> 2, tig = lane & 3;
    int m0 = blockIdx.y * 128, n0 = blockIdx.x * 128;

    float acc[2][8][4];
    #pragma unroll
    for (int i = 0; i < 2; i++)
        #pragma unroll
        for (int j = 0; j < 8; j++)
            #pragma unroll
            for (int c = 0; c < 4; c++) acc[i][j][c] = 0.f;

    // gmem load slots: 2 rows per thread per tile
    int lrow = tid >> 2, lseg = tid & 3;    // rows 0..63 (+64), seg*8 elems
    float4 rAh[2], rAl[2], rBh[2], rBl[2];

    auto gload = [&](int kc0) {
        #pragma unroll
        for (int i = 0; i < 2; i++) {
            int row = lrow + i * 64;
            size_t ga = (size_t)(m0 + row) * K + kc0 + lseg * 8;
            size_t gb = (size_t)(n0 + row) * K + kc0 + lseg * 8;
            rAh[i] = *(const float4*)(Ah + ga);
            rAl[i] = *(const float4*)(Al + ga);
            rBh[i] = *(const float4*)(Bh + gb);
            rBl[i] = *(const float4*)(Bl + gb);
        }
    };
    auto sstore = [&]() {
        #pragma unroll
        for (int i = 0; i < 2; i++) {
            int off = (lrow + i * 64) * GT_STRIDE + lseg * 16;
            *(float4*)(smem + T_AH + off) = rAh[i];
            *(float4*)(smem + T_AL + off) = rAl[i];
            *(float4*)(smem + T_BH + off) = rBh[i];
            *(float4*)(smem + T_BL + off) = rBl[i];
        }
    };

    // ldmatrix per-thread base offsets
    int sub = lane >> 3, rin = lane & 7;
    // A: sub0: rows+0..7 k+0 | sub1: rows+8..15 k+0 | sub2: rows+0..7 k+16B | sub3: rows+8..15 k+16B
    uint32_t aoff = (uint32_t)((wm*32 + (sub & 1)*8 + rin) * GT_STRIDE + (sub >> 1) * 16);
    // B: sub0: rows+0..7 k+0 | sub1: rows+0..7 k+16B | sub2: rows+8..15 k+0 | sub3: rows+8..15 k+16B
    uint32_t boff = (uint32_t)((wn*64 + (sub >> 1)*8 + rin) * GT_STRIDE + (sub & 1) * 16);

    int nch = K >> 5;
    gload(0);
    for (int ch = 0; ch < nch; ch++) {
        __syncthreads();
        sstore();
        __syncthreads();
        if (ch + 1 < nch) gload((ch + 1) << 5);

        #pragma unroll
        for (int ks = 0; ks < 2; ks++) {
            uint32_t fAh[2][4], fAl[2][4], fBh[8][2], fBl[8][2];
            #pragma unroll
            for (int am = 0; am < 2; am++) {
                uint32_t ad = sb + aoff + am * (16 * GT_STRIDE) + ks * 32;
                LDSM_X4(fAh[am][0], fAh[am][1], fAh[am][2], fAh[am][3], ad + T_AH);
                LDSM_X4(fAl[am][0], fAl[am][1], fAl[am][2], fAl[am][3], ad + T_AL);
            }
            #pragma unroll
            for (int bn = 0; bn < 4; bn++) {
                uint32_t bd = sb + boff + bn * (16 * GT_STRIDE) + ks * 32;
                LDSM_X4(fBh[2*bn][0], fBh[2*bn][1], fBh[2*bn+1][0], fBh[2*bn+1][1], bd + T_BH);
                LDSM_X4(fBl[2*bn][0], fBl[2*bn][1], fBl[2*bn+1][0], fBl[2*bn+1][1], bd + T_BL);
            }
            #pragma unroll
            for (int am = 0; am < 2; am++)
                #pragma unroll
                for (int nb = 0; nb < 8; nb++) {
                    MMA_BF16(acc[am][nb], fAh[am], fBh[nb]);
                    MMA_BF16(acc[am][nb], fAh[am], fBl[nb]);
                    MMA_BF16(acc[am][nb], fAl[am], fBh[nb]);
                }
        }
    }

    // epilogue with bias
    #pragma unroll
    for (int am = 0; am < 2; am++) {
        int row = m0 + wm*32 + am*16 + gid;
        #pragma unroll
        for (int nb = 0; nb < 8; nb++) {
            int col = n0 + wn*64 + nb*8 + tig*2;
            float2 bv = *(const float2*)(bias + col);
            float2 o0 = { acc[am][nb][0] + bv.x, acc[am][nb][1] + bv.y };
            float2 o1 = { acc[am][nb][2] + bv.x, acc[am][nb][3] + bv.y };
            *(float2*)(C + (size_t)row * N + col)       = o0;
            *(float2*)(C + (size_t)(row + 8) * N + col) = o1;
        }
    }
}

// ---------------- mask dtype detection ----------------
__global__ void detect_mask_kind(const void* mask)
{
    __shared__ int s_int, s_float;
    if (threadIdx.x == 0) { s_int = 1; s_float = 1; }
    __syncthreads();
    const unsigned int* w = (const unsigned int*)mask;
    int ok_i = 1, ok_f = 1;
    for (int i = threadIdx.x; i < 1024; i += blockDim.x) {
        unsigned int v = w[i];
        if (v > 1u) ok_i = 0;
        if (v != 0u && v != 0x3F800000u) ok_f = 0;
    }
    atomicAnd(&s_int, ok_i);
    atomicAnd(&s_float, ok_f);
    __syncthreads();
    if (threadIdx.x == 0) g_mask_kind = s_int ? 0 : (s_float ? 1 : 2);
}

// ---------------- pair [B,T,T,H] -> biasT [B,H,T,T], folding mask ----------------
__global__ void bias_transpose_kernel(const float* __restrict__ pair,
                                      const void* __restrict__ mask)
{
    __shared__ float sp[128][9];
    __shared__ float addm[128];
    int b = blockIdx.z, i = blockIdx.y, j0 = blockIdx.x * 128;
    int t = threadIdx.x;

    const float* src = pair + (((size_t)(b * TT + i) * TT) + j0) * HH;
    {
        int f = t * 4;
        int tj = f >> 3;
        int h0 = f & 7;
        float4 v = *(const float4*)(src + f);
        sp[tj][h0]   = v.x; sp[tj][h0+1] = v.y;
        sp[tj][h0+2] = v.z; sp[tj][h0+3] = v.w;
    }
    if (t < 128) {
        size_t mi = ((size_t)(b * TT + i)) * TT + j0 + t;
        int kind = g_mask_kind;
        bool mv;
        if (kind == 0)      mv = ((const int*)mask)[mi] != 0;
        else if (kind == 1) mv = ((const float*)mask)[mi] != 0.f;
        else                mv = ((const unsigned char*)mask)[mi] != 0;
        addm[t] = mv ? 0.f : NEGF;
    }
    __syncthreads();
    #pragma unroll
    for (int u = 0; u < 4; u++) {
        int f = t + 256 * u;
        int h = f >> 7;
        int tj = f & 127;
        g_biasT[(((size_t)(b * HH + h) * TT + i) * TT) + j0 + tj] = sp[tj][h] + addm[tj];
    }
}

// ---------------- flash attention: one thread per Q row ----------------
__global__ __launch_bounds__(128, 2)
void flash_kernel(const float* __restrict__ qkv, float* __restrict__ out)
{
    __shared__ float Ks[32][64];
    __shared__ float Vs[32][64];
    __shared__ float Bsm[128][33];

    int tidx = threadIdx.x;
    int bh = blockIdx.y;
    int b = bh >> 3, h = bh & 7;
    int i0 = blockIdx.x * 128;
    int i = i0 + tidx;
    const float scale = 0.125f;

    float qv[64];
    const float* qrow = qkv + (size_t)(b * TT + i) * C3 + h * DD;
    #pragma unroll
    for (int d = 0; d < 64; d += 4) {
        float4 t = *(const float4*)(qrow + d);
        qv[d] = t.x * scale; qv[d+1] = t.y * scale;
        qv[d+2] = t.z * scale; qv[d+3] = t.w * scale;
    }

    float m = -3.0e38f, l = 0.f;
    float acc[64];
    #pragma unroll
    for (int d = 0; d < 64; d++) acc[d] = 0.f;

    const float* kbase = qkv + (size_t)b * TT * C3 + CC + h * DD;
    const float* vbase = kbase + CC;
    const float* bbase = g_biasT + ((size_t)bh * TT + i0) * TT;

    for (int jt = 0; jt < 32; jt++) {
        int j0 = jt * 32;
        __syncthreads();
        #pragma unroll
        for (int u = 0; u < 4; u++) {
            int f = tidx * 4 + u;
            int jj = f >> 4;
            int dd = (f & 15) << 2;
            *(float4*)&Ks[jj][dd] = *(const float4*)(kbase + (size_t)(j0 + jj) * C3 + dd);
            *(float4*)&Vs[jj][dd] = *(const float4*)(vbase + (size_t)(j0 + jj) * C3 + dd);
        }
        #pragma unroll
        for (int u = 0; u < 8; u++) {
            int f = tidx * 8 + u;
            int r = f >> 3;
            int c = (f & 7) << 2;
            float4 bv = *(const float4*)(bbase + (size_t)r * TT + j0 + c);
            Bsm[r][c] = bv.x; Bsm[r][c+1] = bv.y;
            Bsm[r][c+2] = bv.z; Bsm[r][c+3] = bv.w;
        }
        __syncthreads();

        float s[32];
        #pragma unroll
        for (int jj = 0; jj < 32; jj++) {
            float dot = 0.f;
            #pragma unroll
            for (int dd = 0; dd < 64; dd += 4) {
                float4 kv = *(const float4*)&Ks[jj][dd];
                dot += qv[dd] * kv.x + qv[dd+1] * kv.y
                     + qv[dd+2] * kv.z + qv[dd+3] * kv.w;
            }
            s[jj] = dot + Bsm[tidx][jj];
        }
        float tmax = s[0];
        #pragma unroll
        for (int jj = 1; jj < 32; jj++) tmax = fmaxf(tmax, s[jj]);
        float mnew = fmaxf(m, tmax);
        float corr = __expf(m - mnew);
        l *= corr;
        #pragma unroll
        for (int d = 0; d < 64; d++) acc[d] *= corr;
        #pragma unroll
        for (int jj = 0; jj < 32; jj++) {
            float p = __expf(s[jj] - mnew);
            l += p;
            #pragma unroll
            for (int dd = 0; dd < 64; dd += 4) {
                float4 vv = *(const float4*)&Vs[jj][dd];
                acc[dd]   += p * vv.x; acc[dd+1] += p * vv.y;
                acc[dd+2] += p * vv.z; acc[dd+3] += p * vv.w;
            }
        }
        m = mnew;
    }

    float inv = 1.f / l;
    float* orow = out + (size_t)(b * TT + i) * CC + h * DD;
    #pragma unroll
    for (int d = 0; d < 64; d += 4) {
        float4 o;
        o.x = acc[d] * inv;   o.y = acc[d+1] * inv;
        o.z = acc[d+2] * inv; o.w = acc[d+3] * inv;
        *(float4*)(orow + d) = o;
    }
}

// ---------------- launch ----------------
extern "C" void kernel_launch(void* const* d_in, const int* in_sizes, int n_in,
                              void* d_out, int out_size)
{
    const float* x      = (const float*)d_in[0];
    const float* pair   = (const float*)d_in[1];
    const void*  mask   = d_in[2];
    const float* norm_w = (const float*)d_in[3];
    const float* norm_b = (const float*)d_in[4];
    const float* qkv_w  = (const float*)d_in[5];
    const float* qkv_b  = (const float*)d_in[6];
    const float* qln_w  = (const float*)d_in[7];
    const float* qln_b  = (const float*)d_in[8];
    const float* kln_w  = (const float*)d_in[9];
    const float* kln_b  = (const float*)d_in[10];
    const float* proj_w = (const float*)d_in[11];
    const float* proj_b = (const float*)d_in[12];
    float* out = (float*)d_out;

    float *qkvp, *attn;
    __nv_bfloat16 *ah, *al, *wh, *wl;
    cudaGetSymbolAddress((void**)&qkvp, g_qkv);
    cudaGetSymbolAddress((void**)&attn, g_attn);
    cudaGetSymbolAddress((void**)&ah, g_ah);
    cudaGetSymbolAddress((void**)&al, g_al);
    cudaGetSymbolAddress((void**)&wh, g_wh);
    cudaGetSymbolAddress((void**)&wl, g_wl);

    // 1. pre-norm + bf16 split
    ln_split_kernel<<<NROWS, 128>>>(x, norm_w, norm_b, ah, al);
    // 2. split qkv weights + QKV GEMM (HMMA)
    split_kernel<<<(C3*CC/4 + 255)/256, 256>>>(qkv_w, wh, wl, C3*CC/4);
    gemm_tc16<<<dim3(C3/128, NROWS/128), 256>>>(ah, al, wh, wl, qkv_b, qkvp, C3, CC);
    // 3. q / k LayerNorm in place (fp32)
    ln_kernel<<<NROWS, 128>>>(qkvp, qln_w, qln_b, qkvp, C3, 0);
    ln_kernel<<<NROWS, 128>>>(qkvp, kln_w, kln_b, qkvp, C3, CC);
    // 4. mask dtype detection + pair transpose with mask fold
    detect_mask_kind<<<1, 256>>>(mask);
    bias_transpose_kernel<<<dim3(TT/128, TT, BB), 256>>>(pair, mask);
    // 5. flash attention -> [B,T,C]
    flash_kernel<<<dim3(TT/128, BB*HH), 128>>>(qkvp, attn);
    // 6. output projection (HMMA)
    split_kernel<<<(NROWS*CC/4 + 255)/256, 256>>>(attn, ah, al, NROWS*CC/4);
    split_kernel<<<(CC*CC/4 + 255)/256, 256>>>(proj_w, wh, wl, CC*CC/4);
    gemm_tc16<<<dim3(CC/128, NROWS/128), 256>>>(ah, al, wh, wl, proj_b, out, CC, CC);
}

// round 4
// speedup vs baseline: 2.5116x; 1.8537x over previous
#include <cuda_runtime.h>
#include <cuda_bf16.h>
#include <cstdint>

// Problem constants
#define BB 4
#define TT 1024
#define CC 512
#define HH 8
#define DD 64
#define NROWS (BB*TT)          // 4096
#define C3 (3*CC)              // 1536
#define NEGF (-3.402823466e38f)

// -------- scratch (static device globals; allocation-free) --------
__device__ float g_qkv[(size_t)NROWS*C3];         // 24 MB
__device__ float g_biasT[(size_t)BB*HH*TT*TT];    // 128 MB
__device__ int   g_mask_kind;
__device__ __nv_bfloat16 g_ah[(size_t)NROWS*CC];  // A hi (also attn out hi)
__device__ __nv_bfloat16 g_al[(size_t)NROWS*CC];  // A lo
__device__ __nv_bfloat16 g_wh[(size_t)C3*CC];
__device__ __nv_bfloat16 g_wl[(size_t)C3*CC];
__device__ __nv_bfloat16 g_qh[(size_t)NROWS*CC];
__device__ __nv_bfloat16 g_ql[(size_t)NROWS*CC];
__device__ __nv_bfloat16 g_kh[(size_t)NROWS*CC];
__device__ __nv_bfloat16 g_kl[(size_t)NROWS*CC];
__device__ __nv_bfloat16 g_vh[(size_t)NROWS*CC];
__device__ __nv_bfloat16 g_vl[(size_t)NROWS*CC];

// ================ generic-PTX tensor-core helpers ================
__device__ __forceinline__ uint32_t smem_u32(const void* p) {
    uint32_t a;
    asm("{ .reg .u64 t; cvta.to.shared.u64 t, %1; cvt.u32.u64 %0, t; }"
        : "=r"(a) : "l"(p));
    return a;
}
#define LDSM_X4(r0, r1, r2, r3, addr) \
    asm volatile("ldmatrix.sync.aligned.m8n8.x4.shared.b16 {%0,%1,%2,%3}, [%4];" \
        : "=r"(r0), "=r"(r1), "=r"(r2), "=r"(r3) : "r"(addr))
#define LDSM_X4_T(r0, r1, r2, r3, addr) \
    asm volatile("ldmatrix.sync.aligned.m8n8.x4.trans.shared.b16 {%0,%1,%2,%3}, [%4];" \
        : "=r"(r0), "=r"(r1), "=r"(r2), "=r"(r3) : "r"(addr))
#define MMA_BF16(d, a, b) \
    asm volatile("mma.sync.aligned.m16n8k16.row.col.f32.bf16.bf16.f32 " \
        "{%0,%1,%2,%3}, {%4,%5,%6,%7}, {%8,%9}, {%0,%1,%2,%3};" \
        : "+f"((d)[0]), "+f"((d)[1]), "+f"((d)[2]), "+f"((d)[3]) \
        : "r"((a)[0]), "r"((a)[1]), "r"((a)[2]), "r"((a)[3]), \
          "r"((b)[0]), "r"((b)[1]))

__device__ __forceinline__ uint32_t pack_bf16x2(float a, float b) {
    __nv_bfloat162 t = __floats2bfloat162_rn(a, b);
    return *reinterpret_cast<uint32_t*>(&t);
}

// fast exp on FMA pipe: exp(x) = 2^(x*log2e), deg-6 Taylor on frac, rel err ~1.5e-5
__device__ __forceinline__ float fexp(float x) {
    float t = fmaxf(x * 1.4426950408889634f, -126.f);
    float fi = floorf(t);
    float f = t - fi;
    float p = 1.5403530393381609e-4f;
    p = fmaf(p, f, 1.3333558146428443e-3f);
    p = fmaf(p, f, 9.6181291976036826e-3f);
    p = fmaf(p, f, 5.5504108664821580e-2f);
    p = fmaf(p, f, 2.4022650695910071e-1f);
    p = fmaf(p, f, 6.9314718055994531e-1f);
    p = fmaf(p, f, 1.0f);
    int ii = (int)fi;
    return p * __int_as_float((ii + 127) << 23);
}

// ================ LayerNorm core (block of 128 over 512) ================
__device__ __forceinline__ float warp_sum(float v) {
    #pragma unroll
    for (int o = 16; o; o >>= 1) v += __shfl_xor_sync(0xffffffffu, v, o);
    return v;
}

__device__ __forceinline__ void ln_core(float4& v, const float* w, const float* b,
                                        int t, float4& o)
{
    float s  = v.x + v.y + v.z + v.w;
    float sq = v.x*v.x + v.y*v.y + v.z*v.z + v.w*v.w;
    s = warp_sum(s); sq = warp_sum(sq);
    __shared__ float sh[8];
    int wid = t >> 5, lid = t & 31;
    if (lid == 0) { sh[wid] = s; sh[4 + wid] = sq; }
    __syncthreads();
    float ts = sh[0] + sh[1] + sh[2] + sh[3];
    float tq = sh[4] + sh[5] + sh[6] + sh[7];
    float mean = ts * (1.f / CC);
    float var  = tq * (1.f / CC) - mean * mean;
    float rstd = rsqrtf(var + 1e-5f);
    float4 wv = *(const float4*)(w + t * 4);
    float4 bv = *(const float4*)(b + t * 4);
    o.x = (v.x - mean) * rstd * wv.x + bv.x;
    o.y = (v.y - mean) * rstd * wv.y + bv.y;
    o.z = (v.z - mean) * rstd * wv.z + bv.z;
    o.w = (v.w - mean) * rstd * wv.w + bv.w;
}

__device__ __forceinline__ void split_store4(float4 o, __nv_bfloat16* hi,
                                             __nv_bfloat16* lo, size_t base)
{
    float vv[4] = {o.x, o.y, o.z, o.w};
    __nv_bfloat16 h[4]; float r[4];
    #pragma unroll
    for (int u = 0; u < 4; u++) { h[u] = __float2bfloat16(vv[u]); r[u] = vv[u] - __bfloat162float(h[u]); }
    *(__nv_bfloat162*)(hi + base)     = __nv_bfloat162{h[0], h[1]};
    *(__nv_bfloat162*)(hi + base + 2) = __nv_bfloat162{h[2], h[3]};
    *(__nv_bfloat162*)(lo + base)     = __floats2bfloat162_rn(r[0], r[1]);
    *(__nv_bfloat162*)(lo + base + 2) = __floats2bfloat162_rn(r[2], r[3]);
}

// LN + bf16 hi/lo split (pre-norm x)
__global__ void ln_split_kernel(const float* src, const float* __restrict__ w,
                                const float* __restrict__ b,
                                __nv_bfloat16* hi, __nv_bfloat16* lo)
{
    int row = blockIdx.x, t = threadIdx.x;
    float4 v = *(const float4*)(src + (size_t)row * CC + t * 4);
    float4 o;
    ln_core(v, w, b, t, o);
    split_store4(o, hi, lo, (size_t)row * CC + t * 4);
}

// post-QKV: q-LN(+scale fold)+split, k-LN+split, v split
__global__ void qkv_post(const float* __restrict__ qkv,
                         const float* __restrict__ qw, const float* __restrict__ qb,
                         const float* __restrict__ kw, const float* __restrict__ kb)
{
    int row = blockIdx.x, t = threadIdx.x;
    const float* rp = qkv + (size_t)row * C3;
    size_t base = (size_t)row * CC + t * 4;
    // Q: LN, fold scale = D^-0.5/TEMP = 0.125
    float4 v = *(const float4*)(rp + t * 4);
    float4 o;
    ln_core(v, qw, qb, t, o);
    o.x *= 0.125f; o.y *= 0.125f; o.z *= 0.125f; o.w *= 0.125f;
    split_store4(o, g_qh, g_ql, base);
    __syncthreads();
    // K: LN
    v = *(const float4*)(rp + CC + t * 4);
    ln_core(v, kw, kb, t, o);
    split_store4(o, g_kh, g_kl, base);
    // V: plain split
    v = *(const float4*)(rp + 2 * CC + t * 4);
    split_store4(v, g_vh, g_vl, base);
}

// generic fp32 -> bf16 hi/lo split (vec4)
__global__ void split_kernel(const float* __restrict__ src,
                             __nv_bfloat16* hi, __nv_bfloat16* lo, int n4)
{
    int i = blockIdx.x * blockDim.x + threadIdx.x;
    if (i >= n4) return;
    float4 v = ((const float4*)src)[i];
    split_store4(v, hi, lo, (size_t)i * 4);
}

// ================ HMMA bf16 split-GEMM (unchanged from R3) ================
#define GT_STRIDE 80
#define GT_TILE   (128*GT_STRIDE)

__global__ __launch_bounds__(256, 1)
void gemm_tc16(const __nv_bfloat16* __restrict__ Ah, const __nv_bfloat16* __restrict__ Al,
               const __nv_bfloat16* __restrict__ Bh, const __nv_bfloat16* __restrict__ Bl,
               const float* __restrict__ bias, float* __restrict__ C,
               int N, int K)
{
    __shared__ __align__(16) char smem[4 * GT_TILE];
    const int T_AH = 0, T_AL = GT_TILE, T_BH = 2*GT_TILE, T_BL = 3*GT_TILE;
    uint32_t sb = smem_u32(smem);

    int tid = threadIdx.x;
    int wid = tid >> 5, lane = tid & 31;
    int wm = wid >> 1, wn = wid & 1;
    int gid = lane >> 2, tig = lane & 3;
    int m0 = blockIdx.y * 128, n0 = blockIdx.x * 128;

    float acc[2][8][4];
    #pragma unroll
    for (int i = 0; i < 2; i++)
        #pragma unroll
        for (int j = 0; j < 8; j++)
            #pragma unroll
            for (int c = 0; c < 4; c++) acc[i][j][c] = 0.f;

    int lrow = tid >> 2, lseg = tid & 3;
    float4 rAh[2], rAl[2], rBh[2], rBl[2];

    auto gload = [&](int kc0) {
        #pragma unroll
        for (int i = 0; i < 2; i++) {
            int row = lrow + i * 64;
            size_t ga = (size_t)(m0 + row) * K + kc0 + lseg * 8;
            size_t gb = (size_t)(n0 + row) * K + kc0 + lseg * 8;
            rAh[i] = *(const float4*)(Ah + ga);
            rAl[i] = *(const float4*)(Al + ga);
            rBh[i] = *(const float4*)(Bh + gb);
            rBl[i] = *(const float4*)(Bl + gb);
        }
    };
    auto sstore = [&]() {
        #pragma unroll
        for (int i = 0; i < 2; i++) {
            int off = (lrow + i * 64) * GT_STRIDE + lseg * 16;
            *(float4*)(smem + T_AH + off) = rAh[i];
            *(float4*)(smem + T_AL + off) = rAl[i];
            *(float4*)(smem + T_BH + off) = rBh[i];
            *(float4*)(smem + T_BL + off) = rBl[i];
        }
    };

    int sub = lane >> 3, rin = lane & 7;
    uint32_t aoff = (uint32_t)((wm*32 + (sub & 1)*8 + rin) * GT_STRIDE + (sub >> 1) * 16);
    uint32_t boff = (uint32_t)((wn*64 + (sub >> 1)*8 + rin) * GT_STRIDE + (sub & 1) * 16);

    int nch = K >> 5;
    gload(0);
    for (int ch = 0; ch < nch; ch++) {
        __syncthreads();
        sstore();
        __syncthreads();
        if (ch + 1 < nch) gload((ch + 1) << 5);

        #pragma unroll
        for (int ks = 0; ks < 2; ks++) {
            uint32_t fAh[2][4], fAl[2][4], fBh[8][2], fBl[8][2];
            #pragma unroll
            for (int am = 0; am < 2; am++) {
                uint32_t ad = sb + aoff + am * (16 * GT_STRIDE) + ks * 32;
                LDSM_X4(fAh[am][0], fAh[am][1], fAh[am][2], fAh[am][3], ad + T_AH);
                LDSM_X4(fAl[am][0], fAl[am][1], fAl[am][2], fAl[am][3], ad + T_AL);
            }
            #pragma unroll
            for (int bn = 0; bn < 4; bn++) {
                uint32_t bd = sb + boff + bn * (16 * GT_STRIDE) + ks * 32;
                LDSM_X4(fBh[2*bn][0], fBh[2*bn][1], fBh[2*bn+1][0], fBh[2*bn+1][1], bd + T_BH);
                LDSM_X4(fBl[2*bn][0], fBl[2*bn][1], fBl[2*bn+1][0], fBl[2*bn+1][1], bd + T_BL);
            }
            #pragma unroll
            for (int am = 0; am < 2; am++)
                #pragma unroll
                for (int nb = 0; nb < 8; nb++) {
                    MMA_BF16(acc[am][nb], fAh[am], fBh[nb]);
                    MMA_BF16(acc[am][nb], fAh[am], fBl[nb]);
                    MMA_BF16(acc[am][nb], fAl[am], fBh[nb]);
                }
        }
    }

    #pragma unroll
    for (int am = 0; am < 2; am++) {
        int row = m0 + wm*32 + am*16 + gid;
        #pragma unroll
        for (int nb = 0; nb < 8; nb++) {
            int col = n0 + wn*64 + nb*8 + tig*2;
            float2 bv = *(const float2*)(bias + col);
            float2 o0 = { acc[am][nb][0] + bv.x, acc[am][nb][1] + bv.y };
            float2 o1 = { acc[am][nb][2] + bv.x, acc[am][nb][3] + bv.y };
            *(float2*)(C + (size_t)row * N + col)       = o0;
            *(float2*)(C + (size_t)(row + 8) * N + col) = o1;
        }
    }
}

// ---------------- mask dtype detection ----------------
__global__ void detect_mask_kind(const void* mask)
{
    __shared__ int s_int, s_float;
    if (threadIdx.x == 0) { s_int = 1; s_float = 1; }
    __syncthreads();
    const unsigned int* w = (const unsigned int*)mask;
    int ok_i = 1, ok_f = 1;
    for (int i = threadIdx.x; i < 1024; i += blockDim.x) {
        unsigned int v = w[i];
        if (v > 1u) ok_i = 0;
        if (v != 0u && v != 0x3F800000u) ok_f = 0;
    }
    atomicAnd(&s_int, ok_i);
    atomicAnd(&s_float, ok_f);
    __syncthreads();
    if (threadIdx.x == 0) g_mask_kind = s_int ? 0 : (s_float ? 1 : 2);
}

// ---------------- pair [B,T,T,H] -> biasT [B,H,T,T], folding mask ----------------
__global__ void bias_transpose_kernel(const float* __restrict__ pair,
                                      const void* __restrict__ mask)
{
    __shared__ float sp[128][9];
    __shared__ float addm[128];
    int b = blockIdx.z, i = blockIdx.y, j0 = blockIdx.x * 128;
    int t = threadIdx.x;

    const float* src = pair + (((size_t)(b * TT + i) * TT) + j0) * HH;
    {
        int f = t * 4;
        int tj = f >> 3;
        int h0 = f & 7;
        float4 v = *(const float4*)(src + f);
        sp[tj][h0]   = v.x; sp[tj][h0+1] = v.y;
        sp[tj][h0+2] = v.z; sp[tj][h0+3] = v.w;
    }
    if (t < 128) {
        size_t mi = ((size_t)(b * TT + i)) * TT + j0 + t;
        int kind = g_mask_kind;
        bool mv;
        if (kind == 0)      mv = ((const int*)mask)[mi] != 0;
        else if (kind == 1) mv = ((const float*)mask)[mi] != 0.f;
        else                mv = ((const unsigned char*)mask)[mi] != 0;
        addm[t] = mv ? 0.f : NEGF;
    }
    __syncthreads();
    #pragma unroll
    for (int u = 0; u < 4; u++) {
        int f = t + 256 * u;
        int h = f >> 7;
        int tj = f & 127;
        g_biasT[(((size_t)(b * HH + h) * TT + i) * TT) + j0 + tj] = sp[tj][h] + addm[tj];
    }
}

// ================ HMMA flash attention ================
// CTA: 64 Q rows (4 warps x 16), KV tiles of 64, head dim 64.
#define FT_STRIDE 144
#define FS_KH 0
#define FS_KL 9216
#define FS_VH 18432
#define FS_VL 27648
#define FS_BIAS 36864
#define FB_STRIDE 272
#define FSM_TOT (36864 + 64*FB_STRIDE)   // 54272

__global__ __launch_bounds__(128, 3)
void flash_hmma(const __nv_bfloat16* __restrict__ qh, const __nv_bfloat16* __restrict__ ql,
                const __nv_bfloat16* __restrict__ kh, const __nv_bfloat16* __restrict__ kl,
                const __nv_bfloat16* __restrict__ vh, const __nv_bfloat16* __restrict__ vl,
                __nv_bfloat16* __restrict__ oh, __nv_bfloat16* __restrict__ ol)
{
    extern __shared__ char sm[];
    uint32_t sb = smem_u32(sm);
    int tid = threadIdx.x;
    int w = tid >> 5, lane = tid & 31;
    int gid = lane >> 2, tig = lane & 3;
    int sub = lane >> 3, rin = lane & 7;
    int bh = blockIdx.y;
    int b = bh >> 3, h = bh & 7;
    int i0 = blockIdx.x * 64;

    // ---- stage Q tile (hi/lo) into KH/KL slots, extract A-fragments ----
    const __nv_bfloat16* qhp = qh + ((size_t)(b*TT + i0)) * CC + h * DD;
    const __nv_bfloat16* qlp = ql + ((size_t)(b*TT + i0)) * CC + h * DD;
    #pragma unroll
    for (int u = 0; u < 4; u++) {
        int f = u * 128 + tid;
        int row = f >> 3, seg = f & 7;
        *(float4*)(sm + FS_KH + row*FT_STRIDE + seg*16) = *(const float4*)(qhp + (size_t)row*CC + seg*8);
        *(float4*)(sm + FS_KL + row*FT_STRIDE + seg*16) = *(const float4*)(qlp + (size_t)row*CC + seg*8);
    }
    __syncthreads();
    uint32_t qfh[4][4], qfl[4][4];
    {
        uint32_t qa = sb + (uint32_t)((w*16 + (sub & 1)*8 + rin) * FT_STRIDE + (sub >> 1)*16);
        #pragma unroll
        for (int kb = 0; kb < 4; kb++) {
            LDSM_X4(qfh[kb][0], qfh[kb][1], qfh[kb][2], qfh[kb][3], qa + FS_KH + kb*32);
            LDSM_X4(qfl[kb][0], qfl[kb][1], qfl[kb][2], qfl[kb][3], qa + FS_KL + kb*32);
        }
    }

    float accO[8][4];
    #pragma unroll
    for (int nb = 0; nb < 8; nb++)
        #pragma unroll
        for (int c = 0; c < 4; c++) accO[nb][c] = 0.f;
    float mrow0 = -3.0e38f, mrow1 = -3.0e38f;
    float lrow0 = 0.f, lrow1 = 0.f;

    const __nv_bfloat16* khp = kh + ((size_t)(b*TT)) * CC + h * DD;
    const __nv_bfloat16* klp = kl + ((size_t)(b*TT)) * CC + h * DD;
    const __nv_bfloat16* vhp = vh + ((size_t)(b*TT)) * CC + h * DD;
    const __nv_bfloat16* vlp = vl + ((size_t)(b*TT)) * CC + h * DD;
    const float* bbase = g_biasT + ((size_t)bh * TT + i0) * TT;

    // ldmatrix offsets for K (non-trans) and V (trans) fragments
    uint32_t kfo = (uint32_t)(((sub >> 1)*8 + rin) * FT_STRIDE + (sub & 1)*16);
    uint32_t vfo = (uint32_t)(((sub & 1)*8 + rin) * FT_STRIDE + (sub >> 1)*16);

    for (int jt = 0; jt < 16; jt++) {
        int j0 = jt * 64;
        __syncthreads();
        // load K/V tiles (hi/lo)
        #pragma unroll
        for (int u = 0; u < 4; u++) {
            int f = u * 128 + tid;
            int row = f >> 3, seg = f & 7;
            size_t g = (size_t)(j0 + row) * CC + seg * 8;
            int so = row*FT_STRIDE + seg*16;
            *(float4*)(sm + FS_KH + so) = *(const float4*)(khp + g);
            *(float4*)(sm + FS_KL + so) = *(const float4*)(klp + g);
            *(float4*)(sm + FS_VH + so) = *(const float4*)(vhp + g);
            *(float4*)(sm + FS_VL + so) = *(const float4*)(vlp + g);
        }
        // bias tile 64x64
        #pragma unroll
        for (int u = 0; u < 8; u++) {
            int f = u * 128 + tid;
            int row = f >> 4, seg = f & 15;
            *(float4*)(sm + FS_BIAS + row*FB_STRIDE + seg*16) =
                *(const float4*)(bbase + (size_t)row*TT + j0 + seg*4);
        }
        __syncthreads();

        // ---- S = Q K^T + bias  (init accum from bias) ----
        float s[8][4];
        #pragma unroll
        for (int nb = 0; nb < 8; nb++) {
            int brow = w*16 + gid;
            int bcol = (nb*8 + tig*2) * 4;
            float2 b0 = *(const float2*)(sm + FS_BIAS + brow*FB_STRIDE + bcol);
            float2 b1 = *(const float2*)(sm + FS_BIAS + (brow+8)*FB_STRIDE + bcol);
            s[nb][0] = b0.x; s[nb][1] = b0.y; s[nb][2] = b1.x; s[nb][3] = b1.y;
        }
        #pragma unroll
        for (int kb = 0; kb < 4; kb++) {
            #pragma unroll
            for (int nb2 = 0; nb2 < 4; nb2++) {
                uint32_t ka = sb + kfo + (uint32_t)(nb2*16*FT_STRIDE + kb*32);
                uint32_t kh0[2], kh1[2], kl0[2], kl1[2];
                LDSM_X4(kh0[0], kh0[1], kh1[0], kh1[1], ka + FS_KH);
                LDSM_X4(kl0[0], kl0[1], kl1[0], kl1[1], ka + FS_KL);
                MMA_BF16(s[2*nb2],   qfh[kb], kh0);
                MMA_BF16(s[2*nb2],   qfh[kb], kl0);
                MMA_BF16(s[2*nb2],   qfl[kb], kh0);
                MMA_BF16(s[2*nb2+1], qfh[kb], kh1);
                MMA_BF16(s[2*nb2+1], qfh[kb], kl1);
                MMA_BF16(s[2*nb2+1], qfl[kb], kh1);
            }
        }

        // ---- online softmax ----
        float mt0 = s[0][0], mt1 = s[0][2];
        #pragma unroll
        for (int nb = 0; nb < 8; nb++) {
            mt0 = fmaxf(mt0, fmaxf(s[nb][0], s[nb][1]));
            mt1 = fmaxf(mt1, fmaxf(s[nb][2], s[nb][3]));
        }
        mt0 = fmaxf(mt0, __shfl_xor_sync(0xffffffffu, mt0, 1));
        mt0 = fmaxf(mt0, __shfl_xor_sync(0xffffffffu, mt0, 2));
        mt1 = fmaxf(mt1, __shfl_xor_sync(0xffffffffu, mt1, 1));
        mt1 = fmaxf(mt1, __shfl_xor_sync(0xffffffffu, mt1, 2));
        float mn0 = fmaxf(mrow0, mt0), mn1 = fmaxf(mrow1, mt1);
        float c0 = fexp(mrow0 - mn0), c1 = fexp(mrow1 - mn1);
        lrow0 *= c0; lrow1 *= c1;
        #pragma unroll
        for (int nb = 0; nb < 8; nb++) {
            accO[nb][0] *= c0; accO[nb][1] *= c0;
            accO[nb][2] *= c1; accO[nb][3] *= c1;
        }
        #pragma unroll
        for (int nb = 0; nb < 8; nb++) {
            s[nb][0] = fexp(s[nb][0] - mn0);
            s[nb][1] = fexp(s[nb][1] - mn0);
            s[nb][2] = fexp(s[nb][2] - mn1);
            s[nb][3] = fexp(s[nb][3] - mn1);
            lrow0 += s[nb][0] + s[nb][1];
            lrow1 += s[nb][2] + s[nb][3];
        }
        mrow0 = mn0; mrow1 = mn1;

        // ---- O += P V (P split hi/lo in-register) ----
        #pragma unroll
        for (int kb = 0; kb < 4; kb++) {
            uint32_t ph[4], pl[4];
            {
                int ne = 2*kb, no = 2*kb + 1;
                __nv_bfloat162 H;
                H = __floats2bfloat162_rn(s[ne][0], s[ne][1]);
                ph[0] = *reinterpret_cast<uint32_t*>(&H);
                pl[0] = pack_bf16x2(s[ne][0] - __low2float(H), s[ne][1] - __high2float(H));
                H = __floats2bfloat162_rn(s[ne][2], s[ne][3]);
                ph[1] = *reinterpret_cast<uint32_t*>(&H);
                pl[1] = pack_bf16x2(s[ne][2] - __low2float(H), s[ne][3] - __high2float(H));
                H = __floats2bfloat162_rn(s[no][0], s[no][1]);
                ph[2] = *reinterpret_cast<uint32_t*>(&H);
                pl[2] = pack_bf16x2(s[no][0] - __low2float(H), s[no][1] - __high2float(H));
                H = __floats2bfloat162_rn(s[no][2], s[no][3]);
                ph[3] = *reinterpret_cast<uint32_t*>(&H);
                pl[3] = pack_bf16x2(s[no][2] - __low2float(H), s[no][3] - __high2float(H));
            }
            #pragma unroll
            for (int db2 = 0; db2 < 4; db2++) {
                uint32_t va = sb + vfo + (uint32_t)(kb*16*FT_STRIDE + db2*32);
                uint32_t vhe[2], vho[2], vle[2], vlo[2];
                LDSM_X4_T(vhe[0], vhe[1], vho[0], vho[1], va + FS_VH);
                LDSM_X4_T(vle[0], vle[1], vlo[0], vlo[1], va + FS_VL);
                MMA_BF16(accO[2*db2],   ph, vhe);
                MMA_BF16(accO[2*db2],   ph, vle);
                MMA_BF16(accO[2*db2],   pl, vhe);
                MMA_BF16(accO[2*db2+1], ph, vho);
                MMA_BF16(accO[2*db2+1], ph, vlo);
                MMA_BF16(accO[2*db2+1], pl, vho);
            }
        }
    }

    // ---- finalize: reduce l over quad, scale, write bf16 hi/lo ----
    lrow0 += __shfl_xor_sync(0xffffffffu, lrow0, 1);
    lrow0 += __shfl_xor_sync(0xffffffffu, lrow0, 2);
    lrow1 += __shfl_xor_sync(0xffffffffu, lrow1, 1);
    lrow1 += __shfl_xor_sync(0xffffffffu, lrow1, 2);
    float inv0 = 1.f / lrow0, inv1 = 1.f / lrow1;

    size_t r0 = (size_t)(b*TT + i0 + w*16 + gid) * CC + h * DD;
    size_t r1 = r0 + 8 * CC;
    #pragma unroll
    for (int nb = 0; nb < 8; nb++) {
        int col = nb*8 + tig*2;
        float o00 = accO[nb][0]*inv0, o01 = accO[nb][1]*inv0;
        float o10 = accO[nb][2]*inv1, o11 = accO[nb][3]*inv1;
        __nv_bfloat162 H0 = __floats2bfloat162_rn(o00, o01);
        __nv_bfloat162 H1 = __floats2bfloat162_rn(o10, o11);
        *(__nv_bfloat162*)(oh + r0 + col) = H0;
        *(__nv_bfloat162*)(oh + r1 + col) = H1;
        *(__nv_bfloat162*)(ol + r0 + col) =
            __floats2bfloat162_rn(o00 - __low2float(H0), o01 - __high2float(H0));
        *(__nv_bfloat162*)(ol + r1 + col) =
            __floats2bfloat162_rn(o10 - __low2float(H1), o11 - __high2float(H1));
    }
}

// ---------------- launch ----------------
extern "C" void kernel_launch(void* const* d_in, const int* in_sizes, int n_in,
                              void* d_out, int out_size)
{
    const float* x      = (const float*)d_in[0];
    const float* pair   = (const float*)d_in[1];
    const void*  mask   = d_in[2];
    const float* norm_w = (const float*)d_in[3];
    const float* norm_b = (const float*)d_in[4];
    const float* qkv_w  = (const float*)d_in[5];
    const float* qkv_b  = (const float*)d_in[6];
    const float* qln_w  = (const float*)d_in[7];
    const float* qln_b  = (const float*)d_in[8];
    const float* kln_w  = (const float*)d_in[9];
    const float* kln_b  = (const float*)d_in[10];
    const float* proj_w = (const float*)d_in[11];
    const float* proj_b = (const float*)d_in[12];
    float* out = (float*)d_out;

    float *qkvp;
    __nv_bfloat16 *ah, *al, *wh, *wl, *qh, *ql, *kh, *kl, *vh, *vl;
    cudaGetSymbolAddress((void**)&qkvp, g_qkv);
    cudaGetSymbolAddress((void**)&ah, g_ah);
    cudaGetSymbolAddress((void**)&al, g_al);
    cudaGetSymbolAddress((void**)&wh, g_wh);
    cudaGetSymbolAddress((void**)&wl, g_wl);
    cudaGetSymbolAddress((void**)&qh, g_qh);
    cudaGetSymbolAddress((void**)&ql, g_ql);
    cudaGetSymbolAddress((void**)&kh, g_kh);
    cudaGetSymbolAddress((void**)&kl, g_kl);
    cudaGetSymbolAddress((void**)&vh, g_vh);
    cudaGetSymbolAddress((void**)&vl, g_vl);

    cudaFuncSetAttribute(flash_hmma, cudaFuncAttributeMaxDynamicSharedMemorySize, FSM_TOT);

    // 1. pre-norm + bf16 split
    ln_split_kernel<<<NROWS, 128>>>(x, norm_w, norm_b, ah, al);
    // 2. split qkv weights + QKV GEMM (HMMA)
    split_kernel<<<(C3*CC/4 + 255)/256, 256>>>(qkv_w, wh, wl, C3*CC/4);
    gemm_tc16<<<dim3(C3/128, NROWS/128), 256>>>(ah, al, wh, wl, qkv_b, qkvp, C3, CC);
    // 3. q/k LN + scale fold + bf16 splits (fused)
    qkv_post<<<NROWS, 128>>>(qkvp, qln_w, qln_b, kln_w, kln_b);
    // 4. mask dtype detection + pair transpose with mask fold
    detect_mask_kind<<<1, 256>>>(mask);
    bias_transpose_kernel<<<dim3(TT/128, TT, BB), 256>>>(pair, mask);
    // 5. HMMA flash attention -> bf16 hi/lo directly (reuse ah/al)
    flash_hmma<<<dim3(TT/64, BB*HH), 128, FSM_TOT>>>(qh, ql, kh, kl, vh, vl, ah, al);
    // 6. output projection (HMMA)
    split_kernel<<<(CC*CC/4 + 255)/256, 256>>>(proj_w, wh, wl, CC*CC/4);
    gemm_tc16<<<dim3(CC/128, NROWS/128), 256>>>(ah, al, wh, wl, proj_b, out, CC, CC);
}

// round 5
// speedup vs baseline: 2.7656x; 1.1011x over previous
#include <cuda_runtime.h>
#include <cuda_bf16.h>
#include <cstdint>

// Problem constants
#define BB 4
#define TT 1024
#define CC 512
#define HH 8
#define DD 64
#define NROWS (BB*TT)          // 4096
#define C3 (3*CC)              // 1536
#define NEGF (-3.402823466e38f)

// -------- scratch (static device globals; allocation-free) --------
__device__ float g_qkv[(size_t)NROWS*C3];         // 24 MB
__device__ float g_biasT[(size_t)BB*HH*TT*TT];    // 128 MB
__device__ int   g_mask_kind;
__device__ __nv_bfloat16 g_ah[(size_t)NROWS*CC];  // A hi (also attn out hi)
__device__ __nv_bfloat16 g_al[(size_t)NROWS*CC];  // A lo
__device__ __nv_bfloat16 g_wh[(size_t)C3*CC];
__device__ __nv_bfloat16 g_wl[(size_t)C3*CC];
__device__ __nv_bfloat16 g_qh[(size_t)NROWS*CC];
__device__ __nv_bfloat16 g_ql[(size_t)NROWS*CC];
__device__ __nv_bfloat16 g_kh[(size_t)NROWS*CC];
__device__ __nv_bfloat16 g_kl[(size_t)NROWS*CC];
__device__ __nv_bfloat16 g_vh[(size_t)NROWS*CC];
__device__ __nv_bfloat16 g_vl[(size_t)NROWS*CC];

// ================ generic-PTX helpers ================
__device__ __forceinline__ uint32_t smem_u32(const void* p) {
    uint32_t a;
    asm("{ .reg .u64 t; cvta.to.shared.u64 t, %1; cvt.u32.u64 %0, t; }"
        : "=r"(a) : "l"(p));
    return a;
}
#define LDSM_X4(r0, r1, r2, r3, addr) \
    asm volatile("ldmatrix.sync.aligned.m8n8.x4.shared.b16 {%0,%1,%2,%3}, [%4];" \
        : "=r"(r0), "=r"(r1), "=r"(r2), "=r"(r3) : "r"(addr))
#define LDSM_X4_T(r0, r1, r2, r3, addr) \
    asm volatile("ldmatrix.sync.aligned.m8n8.x4.trans.shared.b16 {%0,%1,%2,%3}, [%4];" \
        : "=r"(r0), "=r"(r1), "=r"(r2), "=r"(r3) : "r"(addr))
#define MMA_BF16(d, a, b) \
    asm volatile("mma.sync.aligned.m16n8k16.row.col.f32.bf16.bf16.f32 " \
        "{%0,%1,%2,%3}, {%4,%5,%6,%7}, {%8,%9}, {%0,%1,%2,%3};" \
        : "+f"((d)[0]), "+f"((d)[1]), "+f"((d)[2]), "+f"((d)[3]) \
        : "r"((a)[0]), "r"((a)[1]), "r"((a)[2]), "r"((a)[3]), \
          "r"((b)[0]), "r"((b)[1]))
#define CP_ASYNC16(saddr, gptr) \
    asm volatile("cp.async.cg.shared.global [%0], [%1], 16;" \
        :: "r"(saddr), "l"(gptr))
#define CP_COMMIT() asm volatile("cp.async.commit_group;" ::: "memory")
#define CP_WAIT1()  asm volatile("cp.async.wait_group 1;" ::: "memory")

__device__ __forceinline__ uint32_t pack_bf16x2(float a, float b) {
    __nv_bfloat162 t = __floats2bfloat162_rn(a, b);
    return *reinterpret_cast<uint32_t*>(&t);
}

// fast exp on FMA pipe
__device__ __forceinline__ float fexp(float x) {
    float t = fmaxf(x * 1.4426950408889634f, -126.f);
    float fi = floorf(t);
    float f = t - fi;
    float p = 1.5403530393381609e-4f;
    p = fmaf(p, f, 1.3333558146428443e-3f);
    p = fmaf(p, f, 9.6181291976036826e-3f);
    p = fmaf(p, f, 5.5504108664821580e-2f);
    p = fmaf(p, f, 2.4022650695910071e-1f);
    p = fmaf(p, f, 6.9314718055994531e-1f);
    p = fmaf(p, f, 1.0f);
    int ii = (int)fi;
    return p * __int_as_float((ii + 127) << 23);
}

// ================ LayerNorm core ================
__device__ __forceinline__ float warp_sum(float v) {
    #pragma unroll
    for (int o = 16; o; o >>= 1) v += __shfl_xor_sync(0xffffffffu, v, o);
    return v;
}

__device__ __forceinline__ void ln_core(float4& v, const float* w, const float* b,
                                        int t, float4& o)
{
    float s  = v.x + v.y + v.z + v.w;
    float sq = v.x*v.x + v.y*v.y + v.z*v.z + v.w*v.w;
    s = warp_sum(s); sq = warp_sum(sq);
    __shared__ float sh[8];
    int wid = t >> 5, lid = t & 31;
    if (lid == 0) { sh[wid] = s; sh[4 + wid] = sq; }
    __syncthreads();
    float ts = sh[0] + sh[1] + sh[2] + sh[3];
    float tq = sh[4] + sh[5] + sh[6] + sh[7];
    float mean = ts * (1.f / CC);
    float var  = tq * (1.f / CC) - mean * mean;
    float rstd = rsqrtf(var + 1e-5f);
    float4 wv = *(const float4*)(w + t * 4);
    float4 bv = *(const float4*)(b + t * 4);
    o.x = (v.x - mean) * rstd * wv.x + bv.x;
    o.y = (v.y - mean) * rstd * wv.y + bv.y;
    o.z = (v.z - mean) * rstd * wv.z + bv.z;
    o.w = (v.w - mean) * rstd * wv.w + bv.w;
}

__device__ __forceinline__ void split_store4(float4 o, __nv_bfloat16* hi,
                                             __nv_bfloat16* lo, size_t base)
{
    float vv[4] = {o.x, o.y, o.z, o.w};
    __nv_bfloat16 h[4]; float r[4];
    #pragma unroll
    for (int u = 0; u < 4; u++) { h[u] = __float2bfloat16(vv[u]); r[u] = vv[u] - __bfloat162float(h[u]); }
    *(__nv_bfloat162*)(hi + base)     = __nv_bfloat162{h[0], h[1]};
    *(__nv_bfloat162*)(hi + base + 2) = __nv_bfloat162{h[2], h[3]};
    *(__nv_bfloat162*)(lo + base)     = __floats2bfloat162_rn(r[0], r[1]);
    *(__nv_bfloat162*)(lo + base + 2) = __floats2bfloat162_rn(r[2], r[3]);
}

__global__ void ln_split_kernel(const float* src, const float* __restrict__ w,
                                const float* __restrict__ b,
                                __nv_bfloat16* hi, __nv_bfloat16* lo)
{
    int row = blockIdx.x, t = threadIdx.x;
    float4 v = *(const float4*)(src + (size_t)row * CC + t * 4);
    float4 o;
    ln_core(v, w, b, t, o);
    split_store4(o, hi, lo, (size_t)row * CC + t * 4);
}

__global__ void qkv_post(const float* __restrict__ qkv,
                         const float* __restrict__ qw, const float* __restrict__ qb,
                         const float* __restrict__ kw, const float* __restrict__ kb)
{
    int row = blockIdx.x, t = threadIdx.x;
    const float* rp = qkv + (size_t)row * C3;
    size_t base = (size_t)row * CC + t * 4;
    float4 v = *(const float4*)(rp + t * 4);
    float4 o;
    ln_core(v, qw, qb, t, o);
    o.x *= 0.125f; o.y *= 0.125f; o.z *= 0.125f; o.w *= 0.125f;
    split_store4(o, g_qh, g_ql, base);
    __syncthreads();
    v = *(const float4*)(rp + CC + t * 4);
    ln_core(v, kw, kb, t, o);
    split_store4(o, g_kh, g_kl, base);
    v = *(const float4*)(rp + 2 * CC + t * 4);
    split_store4(v, g_vh, g_vl, base);
}

__global__ void split_kernel(const float* __restrict__ src,
                             __nv_bfloat16* hi, __nv_bfloat16* lo, int n4)
{
    int i = blockIdx.x * blockDim.x + threadIdx.x;
    if (i >= n4) return;
    float4 v = ((const float4*)src)[i];
    split_store4(v, hi, lo, (size_t)i * 4);
}

// ================ HMMA bf16 split-GEMM, cp.async double-buffered ================
#define GT_STRIDE 80
#define GT_TILE   (128*GT_STRIDE)       // 10240
#define G_AH 0
#define G_AL GT_TILE
#define G_BH (2*GT_TILE)
#define G_BL (3*GT_TILE)
#define GBUF  (4*GT_TILE)               // 40960 per buffer
#define GSMEM (2*GBUF)                  // 81920

__global__ __launch_bounds__(256, 1)
void gemm_tc16(const __nv_bfloat16* __restrict__ Ah, const __nv_bfloat16* __restrict__ Al,
               const __nv_bfloat16* __restrict__ Bh, const __nv_bfloat16* __restrict__ Bl,
               const float* __restrict__ bias, float* __restrict__ C,
               int N, int K)
{
    extern __shared__ __align__(16) char smem[];
    uint32_t sb = smem_u32(smem);

    int tid = threadIdx.x;
    int wid = tid >> 5, lane = tid & 31;
    int wm = wid >> 1, wn = wid & 1;
    int gid = lane >> 2, tig = lane & 3;
    int m0 = blockIdx.y * 128, n0 = blockIdx.x * 128;

    float acc[2][8][4];
    #pragma unroll
    for (int i = 0; i < 2; i++)
        #pragma unroll
        for (int j = 0; j < 8; j++)
            #pragma unroll
            for (int c = 0; c < 4; c++) acc[i][j][c] = 0.f;

    int lrow = tid >> 2, lseg = tid & 3;

    auto issue = [&](int kc0, uint32_t bufo) {
        #pragma unroll
        for (int i = 0; i < 2; i++) {
            int row = lrow + i * 64;
            size_t ga = (size_t)(m0 + row) * K + kc0 + lseg * 8;
            size_t gb = (size_t)(n0 + row) * K + kc0 + lseg * 8;
            uint32_t so = sb + bufo + (uint32_t)(row * GT_STRIDE + lseg * 16);
            CP_ASYNC16(so + G_AH, Ah + ga);
            CP_ASYNC16(so + G_AL, Al + ga);
            CP_ASYNC16(so + G_BH, Bh + gb);
            CP_ASYNC16(so + G_BL, Bl + gb);
        }
    };

    int sub = lane >> 3, rin = lane & 7;
    uint32_t aoff = (uint32_t)((wm*32 + (sub & 1)*8 + rin) * GT_STRIDE + (sub >> 1) * 16);
    uint32_t boff = (uint32_t)((wn*64 + (sub >> 1)*8 + rin) * GT_STRIDE + (sub & 1) * 16);

    int nch = K >> 5;
    issue(0, 0); CP_COMMIT();
    issue(32, GBUF); CP_COMMIT();

    for (int ch = 0; ch < nch; ch++) {
        uint32_t bufo = (uint32_t)(ch & 1) * GBUF;
        CP_WAIT1();
        __syncthreads();

        #pragma unroll
        for (int ks = 0; ks < 2; ks++) {
            uint32_t fAh[2][4], fAl[2][4], fBh[8][2], fBl[8][2];
            #pragma unroll
            for (int am = 0; am < 2; am++) {
                uint32_t ad = sb + bufo + aoff + am * (16 * GT_STRIDE) + ks * 32;
                LDSM_X4(fAh[am][0], fAh[am][1], fAh[am][2], fAh[am][3], ad + G_AH);
                LDSM_X4(fAl[am][0], fAl[am][1], fAl[am][2], fAl[am][3], ad + G_AL);
            }
            #pragma unroll
            for (int bn = 0; bn < 4; bn++) {
                uint32_t bd = sb + bufo + boff + bn * (16 * GT_STRIDE) + ks * 32;
                LDSM_X4(fBh[2*bn][0], fBh[2*bn][1], fBh[2*bn+1][0], fBh[2*bn+1][1], bd + G_BH);
                LDSM_X4(fBl[2*bn][0], fBl[2*bn][1], fBl[2*bn+1][0], fBl[2*bn+1][1], bd + G_BL);
            }
            #pragma unroll
            for (int am = 0; am < 2; am++)
                #pragma unroll
                for (int nb = 0; nb < 8; nb++) {
                    MMA_BF16(acc[am][nb], fAh[am], fBh[nb]);
                    MMA_BF16(acc[am][nb], fAh[am], fBl[nb]);
                    MMA_BF16(acc[am][nb], fAl[am], fBh[nb]);
                }
        }
        __syncthreads();
        if (ch + 2 < nch) issue((ch + 2) << 5, bufo);
        CP_COMMIT();
    }

    #pragma unroll
    for (int am = 0; am < 2; am++) {
        int row = m0 + wm*32 + am*16 + gid;
        #pragma unroll
        for (int nb = 0; nb < 8; nb++) {
            int col = n0 + wn*64 + nb*8 + tig*2;
            float2 bv = *(const float2*)(bias + col);
            float2 o0 = { acc[am][nb][0] + bv.x, acc[am][nb][1] + bv.y };
            float2 o1 = { acc[am][nb][2] + bv.x, acc[am][nb][3] + bv.y };
            *(float2*)(C + (size_t)row * N + col)       = o0;
            *(float2*)(C + (size_t)(row + 8) * N + col) = o1;
        }
    }
}

// ---------------- mask dtype detection ----------------
__global__ void detect_mask_kind(const void* mask)
{
    __shared__ int s_int, s_float;
    if (threadIdx.x == 0) { s_int = 1; s_float = 1; }
    __syncthreads();
    const unsigned int* w = (const unsigned int*)mask;
    int ok_i = 1, ok_f = 1;
    for (int i = threadIdx.x; i < 1024; i += blockDim.x) {
        unsigned int v = w[i];
        if (v > 1u) ok_i = 0;
        if (v != 0u && v != 0x3F800000u) ok_f = 0;
    }
    atomicAnd(&s_int, ok_i);
    atomicAnd(&s_float, ok_f);
    __syncthreads();
    if (threadIdx.x == 0) g_mask_kind = s_int ? 0 : (s_float ? 1 : 2);
}

// ---------------- pair [B,T,T,H] -> biasT [B,H,T,T], folding mask ----------------
__global__ void bias_transpose_kernel(const float* __restrict__ pair,
                                      const void* __restrict__ mask)
{
    __shared__ float sp[128][9];
    __shared__ float addm[128];
    int b = blockIdx.z, i = blockIdx.y, j0 = blockIdx.x * 128;
    int t = threadIdx.x;

    const float* src = pair + (((size_t)(b * TT + i) * TT) + j0) * HH;
    {
        int f = t * 4;
        int tj = f >> 3;
        int h0 = f & 7;
        float4 v = *(const float4*)(src + f);
        sp[tj][h0]   = v.x; sp[tj][h0+1] = v.y;
        sp[tj][h0+2] = v.z; sp[tj][h0+3] = v.w;
    }
    if (t < 128) {
        size_t mi = ((size_t)(b * TT + i)) * TT + j0 + t;
        int kind = g_mask_kind;
        bool mv;
        if (kind == 0)      mv = ((const int*)mask)[mi] != 0;
        else if (kind == 1) mv = ((const float*)mask)[mi] != 0.f;
        else                mv = ((const unsigned char*)mask)[mi] != 0;
        addm[t] = mv ? 0.f : NEGF;
    }
    __syncthreads();
    #pragma unroll
    for (int u = 0; u < 4; u++) {
        int f = t + 256 * u;
        int h = f >> 7;
        int tj = f & 127;
        g_biasT[(((size_t)(b * HH + h) * TT + i) * TT) + j0 + tj] = sp[tj][h] + addm[tj];
    }
}

// ================ HMMA flash attention, cp.async double-buffered ================
#define FT_STRIDE 144
#define FS_KH 0
#define FS_KL 9216
#define FS_VH 18432
#define FS_VL 27648
#define FS_BIAS 36864
#define FB_STRIDE 272
#define FBUF (36864 + 64*FB_STRIDE)     // 54272 per buffer
#define FSM_TOT (2*FBUF)                // 108544

__global__ __launch_bounds__(128, 2)
void flash_hmma(const __nv_bfloat16* __restrict__ qh, const __nv_bfloat16* __restrict__ ql,
                const __nv_bfloat16* __restrict__ kh, const __nv_bfloat16* __restrict__ kl,
                const __nv_bfloat16* __restrict__ vh, const __nv_bfloat16* __restrict__ vl,
                __nv_bfloat16* __restrict__ oh, __nv_bfloat16* __restrict__ ol)
{
    extern __shared__ __align__(16) char sm[];
    uint32_t sb = smem_u32(sm);
    int tid = threadIdx.x;
    int w = tid >> 5, lane = tid & 31;
    int gid = lane >> 2, tig = lane & 3;
    int sub = lane >> 3, rin = lane & 7;
    int bh = blockIdx.y;
    int b = bh >> 3, h = bh & 7;
    int i0 = blockIdx.x * 64;

    // ---- stage Q tile (hi/lo) into buf0 KH/KL slots, extract A-fragments ----
    const __nv_bfloat16* qhp = qh + ((size_t)(b*TT + i0)) * CC + h * DD;
    const __nv_bfloat16* qlp = ql + ((size_t)(b*TT + i0)) * CC + h * DD;
    #pragma unroll
    for (int u = 0; u < 4; u++) {
        int f = u * 128 + tid;
        int row = f >> 3, seg = f & 7;
        *(float4*)(sm + FS_KH + row*FT_STRIDE + seg*16) = *(const float4*)(qhp + (size_t)row*CC + seg*8);
        *(float4*)(sm + FS_KL + row*FT_STRIDE + seg*16) = *(const float4*)(qlp + (size_t)row*CC + seg*8);
    }
    __syncthreads();
    uint32_t qfh[4][4], qfl[4][4];
    {
        uint32_t qa = sb + (uint32_t)((w*16 + (sub & 1)*8 + rin) * FT_STRIDE + (sub >> 1)*16);
        #pragma unroll
        for (int kb = 0; kb < 4; kb++) {
            LDSM_X4(qfh[kb][0], qfh[kb][1], qfh[kb][2], qfh[kb][3], qa + FS_KH + kb*32);
            LDSM_X4(qfl[kb][0], qfl[kb][1], qfl[kb][2], qfl[kb][3], qa + FS_KL + kb*32);
        }
    }
    __syncthreads();

    float accO[8][4];
    #pragma unroll
    for (int nb = 0; nb < 8; nb++)
        #pragma unroll
        for (int c = 0; c < 4; c++) accO[nb][c] = 0.f;
    float mrow0 = -3.0e38f, mrow1 = -3.0e38f;
    float lrow0 = 0.f, lrow1 = 0.f;

    const __nv_bfloat16* khp = kh + ((size_t)(b*TT)) * CC + h * DD;
    const __nv_bfloat16* klp = kl + ((size_t)(b*TT)) * CC + h * DD;
    const __nv_bfloat16* vhp = vh + ((size_t)(b*TT)) * CC + h * DD;
    const __nv_bfloat16* vlp = vl + ((size_t)(b*TT)) * CC + h * DD;
    const float* bbase = g_biasT + ((size_t)bh * TT + i0) * TT;

    auto issue_tile = [&](int jt, uint32_t bufo) {
        int j0 = jt * 64;
        #pragma unroll
        for (int u = 0; u < 4; u++) {
            int f = u * 128 + tid;
            int row = f >> 3, seg = f & 7;
            size_t g = (size_t)(j0 + row) * CC + seg * 8;
            uint32_t so = sb + bufo + (uint32_t)(row*FT_STRIDE + seg*16);
            CP_ASYNC16(so + FS_KH, khp + g);
            CP_ASYNC16(so + FS_KL, klp + g);
            CP_ASYNC16(so + FS_VH, vhp + g);
            CP_ASYNC16(so + FS_VL, vlp + g);
        }
        #pragma unroll
        for (int u = 0; u < 8; u++) {
            int f = u * 128 + tid;
            int row = f >> 4, seg = f & 15;
            CP_ASYNC16(sb + bufo + FS_BIAS + (uint32_t)(row*FB_STRIDE + seg*16),
                       bbase + (size_t)row*TT + j0 + seg*4);
        }
    };

    uint32_t kfo = (uint32_t)(((sub >> 1)*8 + rin) * FT_STRIDE + (sub & 1)*16);
    uint32_t vfo = (uint32_t)(((sub & 1)*8 + rin) * FT_STRIDE + (sub >> 1)*16);

    issue_tile(0, 0); CP_COMMIT();
    issue_tile(1, FBUF); CP_COMMIT();

    for (int jt = 0; jt < 16; jt++) {
        uint32_t bufo = (uint32_t)(jt & 1) * FBUF;
        CP_WAIT1();
        __syncthreads();

        // ---- S = Q K^T + bias ----
        float s[8][4];
        #pragma unroll
        for (int nb = 0; nb < 8; nb++) {
            int brow = w*16 + gid;
            int bcol = (nb*8 + tig*2) * 4;
            float2 b0 = *(const float2*)(sm + bufo + FS_BIAS + brow*FB_STRIDE + bcol);
            float2 b1 = *(const float2*)(sm + bufo + FS_BIAS + (brow+8)*FB_STRIDE + bcol);
            s[nb][0] = b0.x; s[nb][1] = b0.y; s[nb][2] = b1.x; s[nb][3] = b1.y;
        }
        #pragma unroll
        for (int kb = 0; kb < 4; kb++) {
            #pragma unroll
            for (int nb2 = 0; nb2 < 4; nb2++) {
                uint32_t ka = sb + bufo + kfo + (uint32_t)(nb2*16*FT_STRIDE + kb*32);
                uint32_t kh0[2], kh1[2], kl0[2], kl1[2];
                LDSM_X4(kh0[0], kh0[1], kh1[0], kh1[1], ka + FS_KH);
                LDSM_X4(kl0[0], kl0[1], kl1[0], kl1[1], ka + FS_KL);
                MMA_BF16(s[2*nb2],   qfh[kb], kh0);
                MMA_BF16(s[2*nb2],   qfh[kb], kl0);
                MMA_BF16(s[2*nb2],   qfl[kb], kh0);
                MMA_BF16(s[2*nb2+1], qfh[kb], kh1);
                MMA_BF16(s[2*nb2+1], qfh[kb], kl1);
                MMA_BF16(s[2*nb2+1], qfl[kb], kh1);
            }
        }

        // ---- online softmax ----
        float mt0 = s[0][0], mt1 = s[0][2];
        #pragma unroll
        for (int nb = 0; nb < 8; nb++) {
            mt0 = fmaxf(mt0, fmaxf(s[nb][0], s[nb][1]));
            mt1 = fmaxf(mt1, fmaxf(s[nb][2], s[nb][3]));
        }
        mt0 = fmaxf(mt0, __shfl_xor_sync(0xffffffffu, mt0, 1));
        mt0 = fmaxf(mt0, __shfl_xor_sync(0xffffffffu, mt0, 2));
        mt1 = fmaxf(mt1, __shfl_xor_sync(0xffffffffu, mt1, 1));
        mt1 = fmaxf(mt1, __shfl_xor_sync(0xffffffffu, mt1, 2));
        float mn0 = fmaxf(mrow0, mt0), mn1 = fmaxf(mrow1, mt1);
        float c0 = fexp(mrow0 - mn0), c1 = fexp(mrow1 - mn1);
        lrow0 *= c0; lrow1 *= c1;
        #pragma unroll
        for (int nb = 0; nb < 8; nb++) {
            accO[nb][0] *= c0; accO[nb][1] *= c0;
            accO[nb][2] *= c1; accO[nb][3] *= c1;
        }
        #pragma unroll
        for (int nb = 0; nb < 8; nb++) {
            s[nb][0] = fexp(s[nb][0] - mn0);
            s[nb][1] = fexp(s[nb][1] - mn0);
            s[nb][2] = fexp(s[nb][2] - mn1);
            s[nb][3] = fexp(s[nb][3] - mn1);
            lrow0 += s[nb][0] + s[nb][1];
            lrow1 += s[nb][2] + s[nb][3];
        }
        mrow0 = mn0; mrow1 = mn1;

        // ---- O += P V ----
        #pragma unroll
        for (int kb = 0; kb < 4; kb++) {
            uint32_t ph[4], pl[4];
            {
                int ne = 2*kb, no = 2*kb + 1;
                __nv_bfloat162 H;
                H = __floats2bfloat162_rn(s[ne][0], s[ne][1]);
                ph[0] = *reinterpret_cast<uint32_t*>(&H);
                pl[0] = pack_bf16x2(s[ne][0] - __low2float(H), s[ne][1] - __high2float(H));
                H = __floats2bfloat162_rn(s[ne][2], s[ne][3]);
                ph[1] = *reinterpret_cast<uint32_t*>(&H);
                pl[1] = pack_bf16x2(s[ne][2] - __low2float(H), s[ne][3] - __high2float(H));
                H = __floats2bfloat162_rn(s[no][0], s[no][1]);
                ph[2] = *reinterpret_cast<uint32_t*>(&H);
                pl[2] = pack_bf16x2(s[no][0] - __low2float(H), s[no][1] - __high2float(H));
                H = __floats2bfloat162_rn(s[no][2], s[no][3]);
                ph[3] = *reinterpret_cast<uint32_t*>(&H);
                pl[3] = pack_bf16x2(s[no][2] - __low2float(H), s[no][3] - __high2float(H));
            }
            #pragma unroll
            for (int db2 = 0; db2 < 4; db2++) {
                uint32_t va = sb + bufo + vfo + (uint32_t)(kb*16*FT_STRIDE + db2*32);
                uint32_t vhe[2], vho[2], vle[2], vlo[2];
                LDSM_X4_T(vhe[0], vhe[1], vho[0], vho[1], va + FS_VH);
                LDSM_X4_T(vle[0], vle[1], vlo[0], vlo[1], va + FS_VL);
                MMA_BF16(accO[2*db2],   ph, vhe);
                MMA_BF16(accO[2*db2],   ph, vle);
                MMA_BF16(accO[2*db2],   pl, vhe);
                MMA_BF16(accO[2*db2+1], ph, vho);
                MMA_BF16(accO[2*db2+1], ph, vlo);
                MMA_BF16(accO[2*db2+1], pl, vho);
            }
        }

        __syncthreads();
        if (jt + 2 < 16) issue_tile(jt + 2, bufo);
        CP_COMMIT();
    }

    // ---- finalize ----
    lrow0 += __shfl_xor_sync(0xffffffffu, lrow0, 1);
    lrow0 += __shfl_xor_sync(0xffffffffu, lrow0, 2);
    lrow1 += __shfl_xor_sync(0xffffffffu, lrow1, 1);
    lrow1 += __shfl_xor_sync(0xffffffffu, lrow1, 2);
    float inv0 = 1.f / lrow0, inv1 = 1.f / lrow1;

    size_t r0 = (size_t)(b*TT + i0 + w*16 + gid) * CC + h * DD;
    size_t r1 = r0 + 8 * CC;
    #pragma unroll
    for (int nb = 0; nb < 8; nb++) {
        int col = nb*8 + tig*2;
        float o00 = accO[nb][0]*inv0, o01 = accO[nb][1]*inv0;
        float o10 = accO[nb][2]*inv1, o11 = accO[nb][3]*inv1;
        __nv_bfloat162 H0 = __floats2bfloat162_rn(o00, o01);
        __nv_bfloat162 H1 = __floats2bfloat162_rn(o10, o11);
        *(__nv_bfloat162*)(oh + r0 + col) = H0;
        *(__nv_bfloat162*)(oh + r1 + col) = H1;
        *(__nv_bfloat162*)(ol + r0 + col) =
            __floats2bfloat162_rn(o00 - __low2float(H0), o01 - __high2float(H0));
        *(__nv_bfloat162*)(ol + r1 + col) =
            __floats2bfloat162_rn(o10 - __low2float(H1), o11 - __high2float(H1));
    }
}

// ---------------- launch ----------------
extern "C" void kernel_launch(void* const* d_in, const int* in_sizes, int n_in,
                              void* d_out, int out_size)
{
    const float* x      = (const float*)d_in[0];
    const float* pair   = (const float*)d_in[1];
    const void*  mask   = d_in[2];
    const float* norm_w = (const float*)d_in[3];
    const float* norm_b = (const float*)d_in[4];
    const float* qkv_w  = (const float*)d_in[5];
    const float* qkv_b  = (const float*)d_in[6];
    const float* qln_w  = (const float*)d_in[7];
    const float* qln_b  = (const float*)d_in[8];
    const float* kln_w  = (const float*)d_in[9];
    const float* kln_b  = (const float*)d_in[10];
    const float* proj_w = (const float*)d_in[11];
    const float* proj_b = (const float*)d_in[12];
    float* out = (float*)d_out;

    float *qkvp;
    __nv_bfloat16 *ah, *al, *wh, *wl, *qh, *ql, *kh, *kl, *vh, *vl;
    cudaGetSymbolAddress((void**)&qkvp, g_qkv);
    cudaGetSymbolAddress((void**)&ah, g_ah);
    cudaGetSymbolAddress((void**)&al, g_al);
    cudaGetSymbolAddress((void**)&wh, g_wh);
    cudaGetSymbolAddress((void**)&wl, g_wl);
    cudaGetSymbolAddress((void**)&qh, g_qh);
    cudaGetSymbolAddress((void**)&ql, g_ql);
    cudaGetSymbolAddress((void**)&kh, g_kh);
    cudaGetSymbolAddress((void**)&kl, g_kl);
    cudaGetSymbolAddress((void**)&vh, g_vh);
    cudaGetSymbolAddress((void**)&vl, g_vl);

    cudaFuncSetAttribute(flash_hmma, cudaFuncAttributeMaxDynamicSharedMemorySize, FSM_TOT);
    cudaFuncSetAttribute(gemm_tc16, cudaFuncAttributeMaxDynamicSharedMemorySize, GSMEM);

    // 0. mask dtype detection (front of stream)
    detect_mask_kind<<<1, 256>>>(mask);
    // 1. pre-norm + bf16 split
    ln_split_kernel<<<NROWS, 128>>>(x, norm_w, norm_b, ah, al);
    // 2. split qkv weights + QKV GEMM (HMMA)
    split_kernel<<<(C3*CC/4 + 255)/256, 256>>>(qkv_w, wh, wl, C3*CC/4);
    gemm_tc16<<<dim3(C3/128, NROWS/128), 256, GSMEM>>>(ah, al, wh, wl, qkv_b, qkvp, C3, CC);
    // 3. q/k LN + scale fold + bf16 splits (fused)
    qkv_post<<<NROWS, 128>>>(qkvp, qln_w, qln_b, kln_w, kln_b);
    // 4. pair transpose with mask fold
    bias_transpose_kernel<<<dim3(TT/128, TT, BB), 256>>>(pair, mask);
    // 5. HMMA flash attention -> bf16 hi/lo directly
    flash_hmma<<<dim3(TT/64, BB*HH), 128, FSM_TOT>>>(qh, ql, kh, kl, vh, vl, ah, al);
    // 6. output projection (HMMA)
    split_kernel<<<(CC*CC/4 + 255)/256, 256>>>(proj_w, wh, wl, CC*CC/4);
    gemm_tc16<<<dim3(CC/128, NROWS/128), 256, GSMEM>>>(ah, al, wh, wl, proj_b, out, CC, CC);
}